// round 9
// baseline (speedup 1.0000x reference)
#include <cuda_runtime.h>
#include <cuda_fp16.h>
#include <cstdint>
#include <cfloat>

#define NPTS   32768
#define DDIM   64
#define KCODES 8192
#define MROWS  128
#define AROW   128                  // bytes per row (64 fp16)
#define ABYTES (MROWS * AROW)       // 16384
#define CHROWS 64
#define CHBYTES (CHROWS * AROW)     // 8192
#define NCHUNK (KCODES / CHROWS)    // 128
#define SMEM_TOTAL (ABYTES + 4 * CHBYTES)   // 49152

__device__ __align__(256) __half g_A[(size_t)NPTS * DDIM];
__device__ __align__(256) __half g_B[(size_t)KCODES * DDIM];
__device__ float  g_zz[NPTS];
__device__ float  g_ee[KCODES];
__device__ float  g_ee2[KCODES];    // 16384 * ee (u' scale)
__device__ int    g_eemax_i;
__device__ int    g_cand[NPTS][16];
__device__ int    g_ccnt[NPTS];
__device__ int    g_idx[NPTS];
__device__ double g_loss;

__device__ __forceinline__ uint32_t smem_u32(const void* p) {
    uint32_t a;
    asm("{ .reg .u64 t; cvta.to.shared.u64 t, %1; cvt.u32.u64 %0, t; }" : "=r"(a) : "l"(p));
    return a;
}
__device__ __forceinline__ void cp16(uint32_t dst, const void* src) {
    asm volatile("cp.async.cg.shared.global [%0], [%1], 16;" :: "r"(dst), "l"(src) : "memory");
}
#define CP_COMMIT() asm volatile("cp.async.commit_group;" ::: "memory")
#define CP_WAIT(n)  asm volatile("cp.async.wait_group %0;" :: "n"(n) : "memory")

#define LDMX4(r, addr) asm volatile( \
    "ldmatrix.sync.aligned.m8n8.x4.shared.b16 {%0,%1,%2,%3}, [%4];" \
    : "=r"((r)[0]), "=r"((r)[1]), "=r"((r)[2]), "=r"((r)[3]) : "r"(addr))

#define MMA(c, a, b0, b1) asm volatile( \
    "mma.sync.aligned.m16n8k16.row.col.f32.f16.f16.f32 " \
    "{%0,%1,%2,%3}, {%4,%5,%6,%7}, {%8,%9}, {%0,%1,%2,%3};" \
    : "+f"((c)[0]), "+f"((c)[1]), "+f"((c)[2]), "+f"((c)[3]) \
    : "r"((a)[0]), "r"((a)[1]), "r"((a)[2]), "r"((a)[3]), "r"(b0), "r"(b1))

// ---------------- 1) fp16 quantize (scaled) + global resets -------------------
__global__ void vq_split(const float* __restrict__ z, const float* __restrict__ e) {
    int t = blockIdx.x * blockDim.x + threadIdx.x;
    if (t == 0) { g_loss = 0.0; g_eemax_i = 0; }
    if (t < NPTS * DDIM) {
        g_A[t] = __float2half_rn(z[t] * 64.f);
    } else if (t < (NPTS + KCODES) * DDIM) {
        int u = t - NPTS * DDIM;
        g_B[u] = __float2half_rn(e[u] * 512.f);
    }
}

// ---------------- 2) norms (+ prescaled ee, global max ||e||^2) ---------------
__global__ void vq_norms(const float* __restrict__ z, const float* __restrict__ e) {
    int t = blockIdx.x * blockDim.x + threadIdx.x;
    if (t < NPTS) {
        const float* p = z + (size_t)t * DDIM;
        float s = 0.f;
        for (int k = 0; k < DDIM; k++) s = __fadd_rn(s, __fmul_rn(p[k], p[k]));
        g_zz[t] = s;
    } else if (t < NPTS + KCODES) {
        const float* p = e + (size_t)(t - NPTS) * DDIM;
        float s = 0.f;
        for (int k = 0; k < DDIM; k++) s = __fadd_rn(s, __fmul_rn(p[k], p[k]));
        g_ee[t - NPTS] = s;
        g_ee2[t - NPTS] = s * 16384.f;
        atomicMax(&g_eemax_i, __float_as_int(s));
    }
}

// ---------------- 3) pass 1: approx GEMM + gated best-2 scan ------------------
__global__ void __launch_bounds__(256, 2) vq_main() {
    extern __shared__ __align__(1024) char sm[];
    const uint32_t sbase = smem_u32(sm);
    const int tid = threadIdx.x, lane = tid & 31, wid = tid >> 5;
    const int wm = wid >> 1, wn = wid & 1;          // 4(M) x 2(N) warps
    const int row0 = blockIdx.x * MROWS;

    #pragma unroll
    for (int q = 0; q < 4; q++) {
        int i = tid + 256 * q;
        int m = i >> 3, g = i & 7;
        cp16(sbase + m * AROW + ((g ^ (m & 7)) << 4),
             (const char*)g_A + (size_t)(row0 + m) * AROW + g * 16);
    }
    CP_COMMIT();

    auto load_chunk = [&](int c, int s) {
        const char* src = (const char*)g_B + (size_t)c * CHROWS * AROW;
        uint32_t d0 = sbase + ABYTES + s * CHBYTES;
        #pragma unroll
        for (int q = 0; q < 2; q++) {
            int i = tid + 256 * q;
            int n = i >> 3, g = i & 7;
            cp16(d0 + n * AROW + ((g ^ (n & 7)) << 4),
                 src + (size_t)n * AROW + g * 16);
        }
        CP_COMMIT();
    };
    load_chunk(0, 0);
    load_chunk(1, 1);

    float v1[4], v2[4]; int i1[4], i2[4];
    #pragma unroll
    for (int r = 0; r < 4; r++) { v1[r] = -FLT_MAX; v2[r] = -FLT_MAX; i1[r] = 0; i2[r] = 0; }

    const uint32_t abase = sbase + (wm * 32 + (lane & 15)) * AROW;
    const uint32_t nbase = (wn * 32 + ((lane >> 4) & 1) * 8 + (lane & 7)) * AROW;
    const int cbase = wn * 32 + 2 * (lane & 3);

    for (int c = 0; c < NCHUNK; c++) {
        if (c + 2 < NCHUNK) load_chunk(c + 2, (c + 2) & 3);
        CP_WAIT(2);
        __syncthreads();
        const uint32_t bbase = sbase + ABYTES + (c & 3) * CHBYTES + nbase;

        float acc[2][4][4];
        #pragma unroll
        for (int mt = 0; mt < 2; mt++)
            #pragma unroll
            for (int c8 = 0; c8 < 4; c8++)
                #pragma unroll
                for (int x = 0; x < 4; x++) acc[mt][c8][x] = 0.f;

        #pragma unroll
        for (int kc = 0; kc < 4; kc++) {
            uint32_t a[2][4], b[2][4];
            const int agr = kc * 2 + (lane >> 4);
            #pragma unroll
            for (int mt = 0; mt < 2; mt++) {
                int m = wm * 32 + mt * 16 + (lane & 15);
                LDMX4(a[mt], abase + mt * (16 * AROW) + ((agr ^ (m & 7)) << 4));
            }
            const int bgr = kc * 2 + ((lane >> 3) & 1);
            #pragma unroll
            for (int np = 0; np < 2; np++) {
                int n = wn * 32 + np * 16 + ((lane >> 4) & 1) * 8 + (lane & 7);
                LDMX4(b[np], bbase + np * (16 * AROW) + ((bgr ^ (n & 7)) << 4));
            }
            #pragma unroll
            for (int mt = 0; mt < 2; mt++)
                #pragma unroll
                for (int np = 0; np < 2; np++) {
                    MMA(acc[mt][2 * np],     a[mt], b[np][0], b[np][1]);
                    MMA(acc[mt][2 * np + 1], a[mt], b[np][2], b[np][3]);
                }
        }

        // scan on u' = acc - 16384*ee (monotone in u). Row-invariant ee2 hoisted.
        float2 e2[4];
        #pragma unroll
        for (int c8 = 0; c8 < 4; c8++)
            e2[c8] = *(const float2*)&g_ee2[c * 64 + cbase + c8 * 8];

        #pragma unroll
        for (int mt = 0; mt < 2; mt++)
            #pragma unroll
            for (int h = 0; h < 2; h++) {
                const int r = mt * 2 + h;
                float u[8];
                #pragma unroll
                for (int c8 = 0; c8 < 4; c8++) {
                    u[2 * c8]     = __fadd_rn(acc[mt][c8][2 * h],     -e2[c8].x);
                    u[2 * c8 + 1] = __fadd_rn(acc[mt][c8][2 * h + 1], -e2[c8].y);
                }
                float m = fmaxf(fmaxf(fmaxf(u[0], u[1]), fmaxf(u[2], u[3])),
                                fmaxf(fmaxf(u[4], u[5]), fmaxf(u[6], u[7])));
                if (m > v2[r]) {   // rare: full top-2 rescan, ascending index
                    #pragma unroll
                    for (int x = 0; x < 8; x++) {
                        int col = c * 64 + cbase + (x >> 1) * 8 + (x & 1);
                        float ux = u[x];
                        if (ux > v2[r]) {
                            if (ux > v1[r]) {
                                v2[r] = v1[r]; i2[r] = i1[r];
                                v1[r] = ux;    i1[r] = col;
                            } else { v2[r] = ux; i2[r] = col; }
                        }
                    }
                }
            }
    }

    CP_WAIT(0);
    __syncthreads();
    float* rv = (float*)(sm + ABYTES);          // [128][16]
    int*   ri = (int*)(sm + ABYTES + 8192);
    #pragma unroll
    for (int r = 0; r < 4; r++) {
        int row_l = wm * 32 + (r >> 1) * 16 + (r & 1) * 8 + (lane >> 2);
        int slot = wn * 8 + (lane & 3) * 2;
        rv[row_l * 16 + slot] = v1[r];     ri[row_l * 16 + slot] = i1[r];
        rv[row_l * 16 + slot + 1] = v2[r]; ri[row_l * 16 + slot + 1] = i2[r];
    }
    __syncthreads();
    if (tid < MROWS) {
        float vmax = -FLT_MAX;
        #pragma unroll
        for (int s = 0; s < 16; s++) vmax = fmaxf(vmax, rv[tid * 16 + s]);
        float eemax = __int_as_float(g_eemax_i);
        // W' = 16384 * (1.46484375e-3*sqrt(zz*eemax) + 5e-5)
        float W = 24.0f * sqrtf(g_zz[row0 + tid] * eemax) + 0.82f;
        float thr = vmax - W;
        int cnt = 0;
        #pragma unroll
        for (int s = 0; s < 16; s++)
            if (rv[tid * 16 + s] >= thr && cnt < 16)
                g_cand[row0 + tid][cnt++] = ri[tid * 16 + s];
        g_ccnt[row0 + tid] = cnt;
    }
}

// ---------------- 4) pass 2: exact refine of survivors ------------------------
__global__ void vq_refine(const float* __restrict__ z, const float* __restrict__ e) {
    int row = blockIdx.x * 8 + (threadIdx.x >> 5);
    int lane = threadIdx.x & 31;
    if (row >= NPTS) return;
    int cnt = g_ccnt[row];
    int besti = g_cand[row][0];
    if (cnt > 1) {
        float zv1 = z[(size_t)row * DDIM + lane];
        float zv2 = z[(size_t)row * DDIM + 32 + lane];
        float zzv = g_zz[row];
        float bd = FLT_MAX; besti = 0x7fffffff;
        for (int t = 0; t < cnt; t++) {
            int idx = g_cand[row][t];
            float p = __fmaf_rn(zv2, e[(size_t)idx * DDIM + 32 + lane],
                                __fmul_rn(zv1, e[(size_t)idx * DDIM + lane]));
            #pragma unroll
            for (int off = 16; off; off >>= 1)
                p += __shfl_xor_sync(0xffffffffu, p, off);
            float d = __fmaf_rn(-2.f, p, __fadd_rn(zzv, g_ee[idx]));
            if (d < bd || (d == bd && idx < besti)) { bd = d; besti = idx; }
        }
    }
    if (lane == 0) g_idx[row] = besti;
}

// ---------------- 5) gather + loss -------------------------------------------
__global__ void vq_out(const float* __restrict__ z, const float* __restrict__ emb,
                       float* __restrict__ out_zq, float* __restrict__ out_idxf) {
    int t = blockIdx.x * blockDim.x + threadIdx.x;
    int nth = gridDim.x * blockDim.x;
    double s = 0.0;
    for (int e4 = t; e4 < NPTS * DDIM / 4; e4 += nth) {
        int row = e4 >> 4;
        float4 zv = ((const float4*)z)[e4];
        float4 ev = *(const float4*)(emb + (size_t)g_idx[row] * DDIM + (e4 & 15) * 4);
        float rx = __fadd_rn(ev.x, -zv.x), ry = __fadd_rn(ev.y, -zv.y);
        float rz = __fadd_rn(ev.z, -zv.z), rw = __fadd_rn(ev.w, -zv.w);
        if (out_zq) {
            float4 o;
            o.x = __fadd_rn(zv.x, rx); o.y = __fadd_rn(zv.y, ry);
            o.z = __fadd_rn(zv.z, rz); o.w = __fadd_rn(zv.w, rw);
            ((float4*)out_zq)[e4] = o;
        }
        s += (double)__fmul_rn(rx, rx) + (double)__fmul_rn(ry, ry)
           + (double)__fmul_rn(rz, rz) + (double)__fmul_rn(rw, rw);
    }
    if (out_idxf && t < NPTS) out_idxf[t] = (float)g_idx[t];
    __shared__ double sd[256];
    sd[threadIdx.x] = s;
    __syncthreads();
    for (int o = 128; o > 0; o >>= 1) {
        if (threadIdx.x < o) sd[threadIdx.x] += sd[threadIdx.x + o];
        __syncthreads();
    }
    if (threadIdx.x == 0) atomicAdd(&g_loss, sd[0]);
}

__global__ void vq_loss(float* __restrict__ out_loss) {
    float m = (float)g_loss / (float)(NPTS * DDIM);
    out_loss[0] = __fadd_rn(__fmul_rn(0.25f, m), m);
}

// ---------------- launch -----------------------------------------------------
extern "C" void kernel_launch(void* const* d_in, const int* in_sizes, int n_in,
                              void* d_out, int out_size) {
    const float* z   = (const float*)d_in[0];
    const float* emb = (const float*)d_in[1];
    if (n_in >= 2 && in_sizes[0] == KCODES * DDIM && in_sizes[1] == NPTS * DDIM) {
        const float* t = z; z = emb; emb = t;
    }
    float* out = (float*)d_out;
    float* out_zq = nullptr; float* out_idxf = nullptr; float* out_loss = nullptr;
    const int NZ = NPTS * DDIM;
    if (out_size >= NZ + NPTS + 1) { out_zq = out; out_idxf = out + NZ; out_loss = out + NZ + NPTS; }
    else if (out_size == NZ)   { out_zq = out; }
    else if (out_size == NPTS) { out_idxf = out; }
    else if (out_size == 1)    { out_loss = out; }
    else                       { out_zq = out; }

    cudaFuncSetAttribute(vq_main, cudaFuncAttributeMaxDynamicSharedMemorySize, SMEM_TOTAL);

    vq_split<<<((NPTS + KCODES) * DDIM + 255) / 256, 256>>>(z, emb);
    vq_norms<<<(NPTS + KCODES + 255) / 256, 256>>>(z, emb);
    vq_main<<<NPTS / MROWS, 256, SMEM_TOTAL>>>();
    vq_refine<<<NPTS / 8, 256>>>(z, emb);
    vq_out<<<512, 256>>>(z, emb, out_zq, out_idxf);
    if (out_loss) vq_loss<<<1, 1>>>(out_loss);
}

// round 10
// speedup vs baseline: 1.2277x; 1.2277x over previous
#include <cuda_runtime.h>
#include <cuda_fp16.h>
#include <cstdint>
#include <cfloat>

#define NPTS   32768
#define DDIM   64
#define KCODES 8192
#define MROWS  128
#define AROW   128                  // bytes per row (64 fp16)
#define ABYTES (MROWS * AROW)       // 16384
#define CHROWS 64
#define CHBYTES (CHROWS * AROW)     // 8192
#define NCHUNK (KCODES / CHROWS)    // 128
#define SMEM_TOTAL (ABYTES + 4 * CHBYTES)   // 49152

__device__ __align__(256) __half g_A[(size_t)NPTS * DDIM];
__device__ __align__(256) __half g_B[(size_t)KCODES * DDIM];
__device__ float  g_zz[NPTS];
__device__ float  g_ee[KCODES];
__device__ float  g_eeC[KCODES];    // 65536 - 16384*ee  (positive-offset u)
__device__ int    g_eemax_i;
__device__ int    g_cand[NPTS][16];
__device__ int    g_ccnt[NPTS];
__device__ int    g_idx[NPTS];
__device__ double g_loss;

__device__ __forceinline__ uint32_t smem_u32(const void* p) {
    uint32_t a;
    asm("{ .reg .u64 t; cvta.to.shared.u64 t, %1; cvt.u32.u64 %0, t; }" : "=r"(a) : "l"(p));
    return a;
}
__device__ __forceinline__ void cp16(uint32_t dst, const void* src) {
    asm volatile("cp.async.cg.shared.global [%0], [%1], 16;" :: "r"(dst), "l"(src) : "memory");
}
#define CP_COMMIT() asm volatile("cp.async.commit_group;" ::: "memory")
#define CP_WAIT(n)  asm volatile("cp.async.wait_group %0;" :: "n"(n) : "memory")

#define LDMX4(r, addr) asm volatile( \
    "ldmatrix.sync.aligned.m8n8.x4.shared.b16 {%0,%1,%2,%3}, [%4];" \
    : "=r"((r)[0]), "=r"((r)[1]), "=r"((r)[2]), "=r"((r)[3]) : "r"(addr))

#define MMA(c, a, b0, b1) asm volatile( \
    "mma.sync.aligned.m16n8k16.row.col.f32.f16.f16.f32 " \
    "{%0,%1,%2,%3}, {%4,%5,%6,%7}, {%8,%9}, {%0,%1,%2,%3};" \
    : "+f"((c)[0]), "+f"((c)[1]), "+f"((c)[2]), "+f"((c)[3]) \
    : "r"((a)[0]), "r"((a)[1]), "r"((a)[2]), "r"((a)[3]), "r"(b0), "r"(b1))

// ---------------- 1) fp16 quantize (scaled) + global resets -------------------
__global__ void vq_split(const float* __restrict__ z, const float* __restrict__ e) {
    int t = blockIdx.x * blockDim.x + threadIdx.x;
    if (t == 0) { g_loss = 0.0; g_eemax_i = 0; }
    if (t < NPTS * DDIM) {
        g_A[t] = __float2half_rn(z[t] * 64.f);
    } else if (t < (NPTS + KCODES) * DDIM) {
        int u = t - NPTS * DDIM;
        g_B[u] = __float2half_rn(e[u] * 512.f);
    }
}

// ---------------- 2) norms (+ offset ee, global max ||e||^2) ------------------
__global__ void vq_norms(const float* __restrict__ z, const float* __restrict__ e) {
    int t = blockIdx.x * blockDim.x + threadIdx.x;
    if (t < NPTS) {
        const float* p = z + (size_t)t * DDIM;
        float s = 0.f;
        for (int k = 0; k < DDIM; k++) s = __fadd_rn(s, __fmul_rn(p[k], p[k]));
        g_zz[t] = s;
    } else if (t < NPTS + KCODES) {
        const float* p = e + (size_t)(t - NPTS) * DDIM;
        float s = 0.f;
        for (int k = 0; k < DDIM; k++) s = __fadd_rn(s, __fmul_rn(p[k], p[k]));
        g_ee[t - NPTS] = s;
        g_eeC[t - NPTS] = 65536.f - s * 16384.f;
        atomicMax(&g_eemax_i, __float_as_int(s));
    }
}

// ---------------- 3) pass 1: approx GEMM + branch-free keyed top-2 ------------
__global__ void __launch_bounds__(256, 2) vq_main() {
    extern __shared__ __align__(1024) char sm[];
    const uint32_t sbase = smem_u32(sm);
    const int tid = threadIdx.x, lane = tid & 31, wid = tid >> 5;
    const int wm = wid >> 1, wn = wid & 1;          // 4(M) x 2(N) warps
    const int row0 = blockIdx.x * MROWS;

    #pragma unroll
    for (int q = 0; q < 4; q++) {
        int i = tid + 256 * q;
        int m = i >> 3, g = i & 7;
        cp16(sbase + m * AROW + ((g ^ (m & 7)) << 4),
             (const char*)g_A + (size_t)(row0 + m) * AROW + g * 16);
    }
    CP_COMMIT();

    auto load_chunk = [&](int c, int s) {
        const char* src = (const char*)g_B + (size_t)c * CHROWS * AROW;
        uint32_t d0 = sbase + ABYTES + s * CHBYTES;
        #pragma unroll
        for (int q = 0; q < 2; q++) {
            int i = tid + 256 * q;
            int n = i >> 3, g = i & 7;
            cp16(d0 + n * AROW + ((g ^ (n & 7)) << 4),
                 src + (size_t)n * AROW + g * 16);
        }
        CP_COMMIT();
    };
    load_chunk(0, 0);
    load_chunk(1, 1);

    int v1[4], v2[4];                // packed keys: float bits | 10-bit colcode
    #pragma unroll
    for (int r = 0; r < 4; r++) { v1[r] = 0; v2[r] = 0; }

    const uint32_t abase = sbase + (wm * 32 + (lane & 15)) * AROW;
    const uint32_t nbase = (wn * 32 + ((lane >> 4) & 1) * 8 + (lane & 7)) * AROW;
    const int cbase = wn * 32 + 2 * (lane & 3);

    for (int c = 0; c < NCHUNK; c++) {
        if (c + 2 < NCHUNK) load_chunk(c + 2, (c + 2) & 3);
        CP_WAIT(2);
        __syncthreads();
        const uint32_t bbase = sbase + ABYTES + (c & 3) * CHBYTES + nbase;

        float acc[2][4][4];
        #pragma unroll
        for (int mt = 0; mt < 2; mt++)
            #pragma unroll
            for (int c8 = 0; c8 < 4; c8++)
                #pragma unroll
                for (int x = 0; x < 4; x++) acc[mt][c8][x] = 0.f;

        #pragma unroll
        for (int kc = 0; kc < 4; kc++) {
            uint32_t a[2][4], b[2][4];
            const int agr = kc * 2 + (lane >> 4);
            #pragma unroll
            for (int mt = 0; mt < 2; mt++) {
                int m = wm * 32 + mt * 16 + (lane & 15);
                LDMX4(a[mt], abase + mt * (16 * AROW) + ((agr ^ (m & 7)) << 4));
            }
            const int bgr = kc * 2 + ((lane >> 3) & 1);
            #pragma unroll
            for (int np = 0; np < 2; np++) {
                int n = wn * 32 + np * 16 + ((lane >> 4) & 1) * 8 + (lane & 7);
                LDMX4(b[np], bbase + np * (16 * AROW) + ((bgr ^ (n & 7)) << 4));
            }
            #pragma unroll
            for (int mt = 0; mt < 2; mt++)
                #pragma unroll
                for (int np = 0; np < 2; np++) {
                    MMA(acc[mt][2 * np],     a[mt], b[np][0], b[np][1]);
                    MMA(acc[mt][2 * np + 1], a[mt], b[np][2], b[np][3]);
                }
        }

        // scan: u = acc + (2^16 - 16384*ee) > 0; key = (bits(u)&~1023)|colcode
        float2 e2[4];
        #pragma unroll
        for (int c8 = 0; c8 < 4; c8++)
            e2[c8] = *(const float2*)&g_eeC[c * 64 + cbase + c8 * 8];
        const int code0 = c * 8;

        #pragma unroll
        for (int mt = 0; mt < 2; mt++)
            #pragma unroll
            for (int h = 0; h < 2; h++) {
                const int r = mt * 2 + h;
                int v1r = v1[r], v2r = v2[r];
                #pragma unroll
                for (int c8 = 0; c8 < 4; c8++) {
                    float u0 = __fadd_rn(acc[mt][c8][2 * h],     e2[c8].x);
                    float u1 = __fadd_rn(acc[mt][c8][2 * h + 1], e2[c8].y);
                    int k0 = (int)((__float_as_uint(u0) & 0xFFFFFC00u)
                                   | (uint32_t)(code0 + c8 * 2));
                    int k1 = (int)((__float_as_uint(u1) & 0xFFFFFC00u)
                                   | (uint32_t)(code0 + c8 * 2 + 1));
                    v2r = max(v2r, min(k0, v1r)); v1r = max(v1r, k0);
                    v2r = max(v2r, min(k1, v1r)); v1r = max(v1r, k1);
                }
                v1[r] = v1r; v2[r] = v2r;
            }
    }

    CP_WAIT(0);
    __syncthreads();
    int* rk = (int*)(sm + ABYTES);              // [128][16] packed keys
    #pragma unroll
    for (int r = 0; r < 4; r++) {
        int row_l = wm * 32 + (r >> 1) * 16 + (r & 1) * 8 + (lane >> 2);
        int slot = wn * 8 + (lane & 3) * 2;
        rk[row_l * 16 + slot]     = v1[r];
        rk[row_l * 16 + slot + 1] = v2[r];
    }
    __syncthreads();
    if (tid < MROWS) {
        int kmax = rk[tid * 16];
        #pragma unroll
        for (int s = 1; s < 16; s++) kmax = max(kmax, rk[tid * 16 + s]);
        float vmax = __uint_as_float((uint32_t)kmax & 0xFFFFFC00u);
        float eemax = __int_as_float(g_eemax_i);
        // W = 16384*(1.46e-3*sqrt(zz*eemax)+5e-5) + 16 (key-quantization margin)
        float W = 24.0f * sqrtf(g_zz[row0 + tid] * eemax) + 17.0f;
        uint32_t thr = __float_as_uint(vmax - W);
        int cnt = 0;
        #pragma unroll
        for (int s = 0; s < 16; s++) {
            uint32_t k = (uint32_t)rk[tid * 16 + s];
            if (k >= thr && cnt < 16) {
                int code = k & 1023;
                int cc = code >> 3, c8 = (code >> 1) & 3, b = code & 1;
                int wn_s = s >> 3, q = (s >> 1) & 3;
                g_cand[row0 + tid][cnt++] = cc * 64 + wn_s * 32 + q * 2 + c8 * 8 + b;
            }
        }
        g_ccnt[row0 + tid] = cnt;
    }
}

// ---------------- 4) pass 2: exact refine of survivors ------------------------
__global__ void vq_refine(const float* __restrict__ z, const float* __restrict__ e) {
    int row = blockIdx.x * 8 + (threadIdx.x >> 5);
    int lane = threadIdx.x & 31;
    if (row >= NPTS) return;
    int cnt = g_ccnt[row];
    int besti = g_cand[row][0];
    if (cnt > 1) {
        float zv1 = z[(size_t)row * DDIM + lane];
        float zv2 = z[(size_t)row * DDIM + 32 + lane];
        float zzv = g_zz[row];
        float bd = FLT_MAX; besti = 0x7fffffff;
        for (int t = 0; t < cnt; t++) {
            int idx = g_cand[row][t];
            float p = __fmaf_rn(zv2, e[(size_t)idx * DDIM + 32 + lane],
                                __fmul_rn(zv1, e[(size_t)idx * DDIM + lane]));
            #pragma unroll
            for (int off = 16; off; off >>= 1)
                p += __shfl_xor_sync(0xffffffffu, p, off);
            float d = __fmaf_rn(-2.f, p, __fadd_rn(zzv, g_ee[idx]));
            if (d < bd || (d == bd && idx < besti)) { bd = d; besti = idx; }
        }
    }
    if (lane == 0) g_idx[row] = besti;
}

// ---------------- 5) gather + loss -------------------------------------------
__global__ void vq_out(const float* __restrict__ z, const float* __restrict__ emb,
                       float* __restrict__ out_zq, float* __restrict__ out_idxf) {
    int t = blockIdx.x * blockDim.x + threadIdx.x;
    int nth = gridDim.x * blockDim.x;
    double s = 0.0;
    for (int e4 = t; e4 < NPTS * DDIM / 4; e4 += nth) {
        int row = e4 >> 4;
        float4 zv = ((const float4*)z)[e4];
        float4 ev = *(const float4*)(emb + (size_t)g_idx[row] * DDIM + (e4 & 15) * 4);
        float rx = __fadd_rn(ev.x, -zv.x), ry = __fadd_rn(ev.y, -zv.y);
        float rz = __fadd_rn(ev.z, -zv.z), rw = __fadd_rn(ev.w, -zv.w);
        if (out_zq) {
            float4 o;
            o.x = __fadd_rn(zv.x, rx); o.y = __fadd_rn(zv.y, ry);
            o.z = __fadd_rn(zv.z, rz); o.w = __fadd_rn(zv.w, rw);
            ((float4*)out_zq)[e4] = o;
        }
        s += (double)__fmul_rn(rx, rx) + (double)__fmul_rn(ry, ry)
           + (double)__fmul_rn(rz, rz) + (double)__fmul_rn(rw, rw);
    }
    if (out_idxf && t < NPTS) out_idxf[t] = (float)g_idx[t];
    __shared__ double sd[256];
    sd[threadIdx.x] = s;
    __syncthreads();
    for (int o = 128; o > 0; o >>= 1) {
        if (threadIdx.x < o) sd[threadIdx.x] += sd[threadIdx.x + o];
        __syncthreads();
    }
    if (threadIdx.x == 0) atomicAdd(&g_loss, sd[0]);
}

__global__ void vq_loss(float* __restrict__ out_loss) {
    float m = (float)g_loss / (float)(NPTS * DDIM);
    out_loss[0] = __fadd_rn(__fmul_rn(0.25f, m), m);
}

// ---------------- launch -----------------------------------------------------
extern "C" void kernel_launch(void* const* d_in, const int* in_sizes, int n_in,
                              void* d_out, int out_size) {
    const float* z   = (const float*)d_in[0];
    const float* emb = (const float*)d_in[1];
    if (n_in >= 2 && in_sizes[0] == KCODES * DDIM && in_sizes[1] == NPTS * DDIM) {
        const float* t = z; z = emb; emb = t;
    }
    float* out = (float*)d_out;
    float* out_zq = nullptr; float* out_idxf = nullptr; float* out_loss = nullptr;
    const int NZ = NPTS * DDIM;
    if (out_size >= NZ + NPTS + 1) { out_zq = out; out_idxf = out + NZ; out_loss = out + NZ + NPTS; }
    else if (out_size == NZ)   { out_zq = out; }
    else if (out_size == NPTS) { out_idxf = out; }
    else if (out_size == 1)    { out_loss = out; }
    else                       { out_zq = out; }

    cudaFuncSetAttribute(vq_main, cudaFuncAttributeMaxDynamicSharedMemorySize, SMEM_TOTAL);

    vq_split<<<((NPTS + KCODES) * DDIM + 255) / 256, 256>>>(z, emb);
    vq_norms<<<(NPTS + KCODES + 255) / 256, 256>>>(z, emb);
    vq_main<<<NPTS / MROWS, 256, SMEM_TOTAL>>>();
    vq_refine<<<NPTS / 8, 256>>>(z, emb);
    vq_out<<<512, 256>>>(z, emb, out_zq, out_idxf);
    if (out_loss) vq_loss<<<1, 1>>>(out_loss);
}

// round 11
// speedup vs baseline: 1.4141x; 1.1518x over previous
#include <cuda_runtime.h>
#include <cuda_fp16.h>
#include <cstdint>
#include <cfloat>

#define NPTS   32768
#define DDIM   64
#define KCODES 8192
#define MROWS  128
#define AROW   128                    // bytes per row (64 fp16)
#define NSTAGE 6
#define CHROWS 64
#define CHBYTES (CHROWS * AROW)       // 8192
#define NCHUNK (KCODES / CHROWS)      // 128
#define SM_A   (NSTAGE * CHBYTES)     // 49152
#define SM_EE  (SM_A + MROWS * AROW)  // 65536
#define SMEM_TOTAL (SM_EE + KCODES * 4)   // 98304

__device__ __align__(256) __half g_A[(size_t)NPTS * DDIM];
__device__ __align__(256) __half g_B[(size_t)KCODES * DDIM];
__device__ float  g_zz[NPTS];
__device__ float  g_ee[KCODES];
__device__ float  g_eeC[KCODES];      // 65536 - 16384*ee
__device__ int    g_eemax_i;
__device__ int    g_cand[NPTS][16];
__device__ int    g_ccnt[NPTS];
__device__ int    g_idx[NPTS];
__device__ double g_loss;

__device__ __forceinline__ uint32_t smem_u32(const void* p) {
    uint32_t a;
    asm("{ .reg .u64 t; cvta.to.shared.u64 t, %1; cvt.u32.u64 %0, t; }" : "=r"(a) : "l"(p));
    return a;
}
__device__ __forceinline__ void cp16(uint32_t dst, const void* src) {
    asm volatile("cp.async.cg.shared.global [%0], [%1], 16;" :: "r"(dst), "l"(src) : "memory");
}
#define CP_COMMIT() asm volatile("cp.async.commit_group;" ::: "memory")
#define CP_WAIT(n)  asm volatile("cp.async.wait_group %0;" :: "n"(n) : "memory")

#define LDMX4(r, addr) asm volatile( \
    "ldmatrix.sync.aligned.m8n8.x4.shared.b16 {%0,%1,%2,%3}, [%4];" \
    : "=r"((r)[0]), "=r"((r)[1]), "=r"((r)[2]), "=r"((r)[3]) : "r"(addr))

#define MMA(c, a, b0, b1) asm volatile( \
    "mma.sync.aligned.m16n8k16.row.col.f32.f16.f16.f32 " \
    "{%0,%1,%2,%3}, {%4,%5,%6,%7}, {%8,%9}, {%0,%1,%2,%3};" \
    : "+f"((c)[0]), "+f"((c)[1]), "+f"((c)[2]), "+f"((c)[3]) \
    : "r"((a)[0]), "r"((a)[1]), "r"((a)[2]), "r"((a)[3]), "r"(b0), "r"(b1))

// ---------------- 1) fp16 quantize (scaled) + global resets -------------------
__global__ void vq_split(const float* __restrict__ z, const float* __restrict__ e) {
    int t = blockIdx.x * blockDim.x + threadIdx.x;
    if (t == 0) { g_loss = 0.0; g_eemax_i = 0; }
    if (t < NPTS * DDIM) {
        g_A[t] = __float2half_rn(z[t] * 64.f);
    } else if (t < (NPTS + KCODES) * DDIM) {
        int u = t - NPTS * DDIM;
        g_B[u] = __float2half_rn(e[u] * 512.f);
    }
}

// ---------------- 2) norms (+ offset ee, global max ||e||^2) ------------------
__global__ void vq_norms(const float* __restrict__ z, const float* __restrict__ e) {
    int t = blockIdx.x * blockDim.x + threadIdx.x;
    if (t < NPTS) {
        const float* p = z + (size_t)t * DDIM;
        float s = 0.f;
        for (int k = 0; k < DDIM; k++) s = __fadd_rn(s, __fmul_rn(p[k], p[k]));
        g_zz[t] = s;
    } else if (t < NPTS + KCODES) {
        const float* p = e + (size_t)(t - NPTS) * DDIM;
        float s = 0.f;
        for (int k = 0; k < DDIM; k++) s = __fadd_rn(s, __fmul_rn(p[k], p[k]));
        g_ee[t - NPTS] = s;
        g_eeC[t - NPTS] = 65536.f - s * 16384.f;
        atomicMax(&g_eemax_i, __float_as_int(s));
    }
}

// ---------------- 3) pass 1: approx GEMM + keyed top-2 (A in regs) ------------
__global__ void __launch_bounds__(256, 2) vq_main() {
    extern __shared__ __align__(1024) char sm[];
    const uint32_t sbase = smem_u32(sm);
    const int tid = threadIdx.x, lane = tid & 31, wid = tid >> 5;
    const int wm = wid >> 1, wn = wid & 1;          // 4(M) x 2(N) warps
    const int row0 = blockIdx.x * MROWS;

    // prologue loads: A tile + eeC table (one group), then B chunks 0..3
    #pragma unroll
    for (int q = 0; q < 4; q++) {
        int i = tid + 256 * q;
        int m = i >> 3, g = i & 7;
        cp16(sbase + SM_A + m * AROW + ((g ^ (m & 7)) << 4),
             (const char*)g_A + (size_t)(row0 + m) * AROW + g * 16);
    }
    #pragma unroll
    for (int q = 0; q < 8; q++) {
        int i = tid + 256 * q;
        cp16(sbase + SM_EE + i * 16, (const char*)g_eeC + i * 16);
    }
    CP_COMMIT();

    auto load_chunk = [&](int c) {
        const char* src = (const char*)g_B + (size_t)c * CHROWS * AROW;
        uint32_t d0 = sbase + (uint32_t)(c % NSTAGE) * CHBYTES;
        #pragma unroll
        for (int q = 0; q < 2; q++) {
            int i = tid + 256 * q;
            int n = i >> 3, g = i & 7;
            cp16(d0 + n * AROW + ((g ^ (n & 7)) << 4),
                 src + (size_t)n * AROW + g * 16);
        }
        CP_COMMIT();
    };
    load_chunk(0); load_chunk(1); load_chunk(2); load_chunk(3);

    CP_WAIT(4);                       // A + eeC resident
    __syncthreads();

    // A fragments -> registers, once
    uint32_t aF[4][2][4];
    {
        const uint32_t abase = sbase + SM_A + (wm * 32 + (lane & 15)) * AROW;
        #pragma unroll
        for (int kc = 0; kc < 4; kc++) {
            const int agr = kc * 2 + (lane >> 4);
            const uint32_t aoff = (uint32_t)((agr ^ (lane & 7)) << 4);
            #pragma unroll
            for (int mt = 0; mt < 2; mt++)
                LDMX4(aF[kc][mt], abase + mt * (16 * AROW) + aoff);
        }
    }

    int v1[4], v2[4];                 // packed keys: float bits | 10-bit code
    #pragma unroll
    for (int r = 0; r < 4; r++) { v1[r] = 0; v2[r] = 0; }

    const uint32_t nbase = (wn * 32 + ((lane >> 4) & 1) * 8 + (lane & 7)) * AROW;
    const int cbase = wn * 32 + 2 * (lane & 3);

    auto compute = [&](int c) {
        const uint32_t bbase = sbase + (uint32_t)(c % NSTAGE) * CHBYTES + nbase;
        // acc init = eeC for this chunk's columns (replaces per-value FADD)
        float2 e2[4];
        #pragma unroll
        for (int c8 = 0; c8 < 4; c8++)
            e2[c8] = *(const float2*)(sm + SM_EE + (c * 64 + cbase + c8 * 8) * 4);
        float acc[2][4][4];
        #pragma unroll
        for (int mt = 0; mt < 2; mt++)
            #pragma unroll
            for (int c8 = 0; c8 < 4; c8++) {
                acc[mt][c8][0] = e2[c8].x; acc[mt][c8][1] = e2[c8].y;
                acc[mt][c8][2] = e2[c8].x; acc[mt][c8][3] = e2[c8].y;
            }
        #pragma unroll
        for (int kc = 0; kc < 4; kc++) {
            uint32_t b[2][4];
            const int bgr = kc * 2 + ((lane >> 3) & 1);
            const uint32_t boff = (uint32_t)((bgr ^ (lane & 7)) << 4);
            #pragma unroll
            for (int np = 0; np < 2; np++)
                LDMX4(b[np], bbase + np * (16 * AROW) + boff);
            #pragma unroll
            for (int mt = 0; mt < 2; mt++)
                #pragma unroll
                for (int np = 0; np < 2; np++) {
                    MMA(acc[mt][2 * np],     aF[kc][mt], b[np][0], b[np][1]);
                    MMA(acc[mt][2 * np + 1], aF[kc][mt], b[np][2], b[np][3]);
                }
        }
        const int code0 = c * 8;
        #pragma unroll
        for (int mt = 0; mt < 2; mt++)
            #pragma unroll
            for (int h = 0; h < 2; h++) {
                const int r = mt * 2 + h;
                int v1r = v1[r], v2r = v2[r];
                #pragma unroll
                for (int c8 = 0; c8 < 4; c8++) {
                    int k0 = (int)((__float_as_uint(acc[mt][c8][2 * h]) & 0xFFFFFC00u)
                                   | (uint32_t)(code0 + c8 * 2));
                    int k1 = (int)((__float_as_uint(acc[mt][c8][2 * h + 1]) & 0xFFFFFC00u)
                                   | (uint32_t)(code0 + c8 * 2 + 1));
                    v2r = max(v2r, min(k0, v1r)); v1r = max(v1r, k0);
                    v2r = max(v2r, min(k1, v1r)); v1r = max(v1r, k1);
                }
                v1[r] = v1r; v2[r] = v2r;
            }
    };

    for (int p = 0; p < 64; p++) {
        if (p < 63) { CP_WAIT(2); } else { CP_WAIT(0); }
        __syncthreads();
        if (p < 62) { load_chunk(2 * p + 4); load_chunk(2 * p + 5); }
        compute(2 * p);
        compute(2 * p + 1);
    }

    __syncthreads();
    int* rk = (int*)(sm + SM_A);                // [128][16] packed keys
    #pragma unroll
    for (int r = 0; r < 4; r++) {
        int row_l = wm * 32 + (r >> 1) * 16 + (r & 1) * 8 + (lane >> 2);
        int slot = wn * 8 + (lane & 3) * 2;
        rk[row_l * 16 + slot]     = v1[r];
        rk[row_l * 16 + slot + 1] = v2[r];
    }
    __syncthreads();
    if (tid < MROWS) {
        int kmax = rk[tid * 16];
        #pragma unroll
        for (int s = 1; s < 16; s++) kmax = max(kmax, rk[tid * 16 + s]);
        float vmax = __uint_as_float((uint32_t)kmax & 0xFFFFFC00u);
        float eemax = __int_as_float(g_eemax_i);
        float W = 24.0f * sqrtf(g_zz[row0 + tid] * eemax) + 18.0f;
        uint32_t thr = __float_as_uint(vmax - W);
        int cnt = 0;
        #pragma unroll
        for (int s = 0; s < 16; s++) {
            uint32_t k = (uint32_t)rk[tid * 16 + s];
            if (k >= thr && cnt < 16) {
                int code = k & 1023;
                int cc = code >> 3, c8 = (code >> 1) & 3, b = code & 1;
                int wn_s = s >> 3, q = (s >> 1) & 3;
                g_cand[row0 + tid][cnt++] = cc * 64 + wn_s * 32 + q * 2 + c8 * 8 + b;
            }
        }
        g_ccnt[row0 + tid] = cnt;
    }
}

// ---------------- 4) pass 2: exact refine of survivors ------------------------
__global__ void vq_refine(const float* __restrict__ z, const float* __restrict__ e) {
    int row = blockIdx.x * 8 + (threadIdx.x >> 5);
    int lane = threadIdx.x & 31;
    if (row >= NPTS) return;
    int cnt = g_ccnt[row];
    int besti = g_cand[row][0];
    if (cnt > 1) {
        float zv1 = z[(size_t)row * DDIM + lane];
        float zv2 = z[(size_t)row * DDIM + 32 + lane];
        float zzv = g_zz[row];
        float bd = FLT_MAX; besti = 0x7fffffff;
        for (int t = 0; t < cnt; t++) {
            int idx = g_cand[row][t];
            float p = __fmaf_rn(zv2, e[(size_t)idx * DDIM + 32 + lane],
                                __fmul_rn(zv1, e[(size_t)idx * DDIM + lane]));
            #pragma unroll
            for (int off = 16; off; off >>= 1)
                p += __shfl_xor_sync(0xffffffffu, p, off);
            float d = __fmaf_rn(-2.f, p, __fadd_rn(zzv, g_ee[idx]));
            if (d < bd || (d == bd && idx < besti)) { bd = d; besti = idx; }
        }
    }
    if (lane == 0) g_idx[row] = besti;
}

// ---------------- 5) gather + loss -------------------------------------------
__global__ void vq_out(const float* __restrict__ z, const float* __restrict__ emb,
                       float* __restrict__ out_zq, float* __restrict__ out_idxf) {
    int t = blockIdx.x * blockDim.x + threadIdx.x;
    int nth = gridDim.x * blockDim.x;
    double s = 0.0;
    for (int e4 = t; e4 < NPTS * DDIM / 4; e4 += nth) {
        int row = e4 >> 4;
        float4 zv = ((const float4*)z)[e4];
        float4 ev = *(const float4*)(emb + (size_t)g_idx[row] * DDIM + (e4 & 15) * 4);
        float rx = __fadd_rn(ev.x, -zv.x), ry = __fadd_rn(ev.y, -zv.y);
        float rz = __fadd_rn(ev.z, -zv.z), rw = __fadd_rn(ev.w, -zv.w);
        if (out_zq) {
            float4 o;
            o.x = __fadd_rn(zv.x, rx); o.y = __fadd_rn(zv.y, ry);
            o.z = __fadd_rn(zv.z, rz); o.w = __fadd_rn(zv.w, rw);
            ((float4*)out_zq)[e4] = o;
        }
        s += (double)__fmul_rn(rx, rx) + (double)__fmul_rn(ry, ry)
           + (double)__fmul_rn(rz, rz) + (double)__fmul_rn(rw, rw);
    }
    if (out_idxf && t < NPTS) out_idxf[t] = (float)g_idx[t];
    __shared__ double sd[256];
    sd[threadIdx.x] = s;
    __syncthreads();
    for (int o = 128; o > 0; o >>= 1) {
        if (threadIdx.x < o) sd[threadIdx.x] += sd[threadIdx.x + o];
        __syncthreads();
    }
    if (threadIdx.x == 0) atomicAdd(&g_loss, sd[0]);
}

__global__ void vq_loss(float* __restrict__ out_loss) {
    float m = (float)g_loss / (float)(NPTS * DDIM);
    out_loss[0] = __fadd_rn(__fmul_rn(0.25f, m), m);
}

// ---------------- launch -----------------------------------------------------
extern "C" void kernel_launch(void* const* d_in, const int* in_sizes, int n_in,
                              void* d_out, int out_size) {
    const float* z   = (const float*)d_in[0];
    const float* emb = (const float*)d_in[1];
    if (n_in >= 2 && in_sizes[0] == KCODES * DDIM && in_sizes[1] == NPTS * DDIM) {
        const float* t = z; z = emb; emb = t;
    }
    float* out = (float*)d_out;
    float* out_zq = nullptr; float* out_idxf = nullptr; float* out_loss = nullptr;
    const int NZ = NPTS * DDIM;
    if (out_size >= NZ + NPTS + 1) { out_zq = out; out_idxf = out + NZ; out_loss = out + NZ + NPTS; }
    else if (out_size == NZ)   { out_zq = out; }
    else if (out_size == NPTS) { out_idxf = out; }
    else if (out_size == 1)    { out_loss = out; }
    else                       { out_zq = out; }

    cudaFuncSetAttribute(vq_main, cudaFuncAttributeMaxDynamicSharedMemorySize, SMEM_TOTAL);

    vq_split<<<((NPTS + KCODES) * DDIM + 255) / 256, 256>>>(z, emb);
    vq_norms<<<(NPTS + KCODES + 255) / 256, 256>>>(z, emb);
    vq_main<<<NPTS / MROWS, 256, SMEM_TOTAL>>>();
    vq_refine<<<NPTS / 8, 256>>>(z, emb);
    vq_out<<<1024, 256>>>(z, emb, out_zq, out_idxf);
    if (out_loss) vq_loss<<<1, 1>>>(out_loss);
}

// round 13
// speedup vs baseline: 1.5025x; 1.0625x over previous
#include <cuda_runtime.h>
#include <cuda_fp16.h>
#include <cstdint>
#include <cfloat>

#define NPTS   32768
#define DDIM   64
#define KCODES 8192
#define MROWS  128
#define AROW   128                    // bytes per row (64 fp16)
#define NSTAGE 6
#define CHROWS 64
#define CHBYTES (CHROWS * AROW)       // 8192
#define NCHUNK (KCODES / CHROWS)      // 128
#define SM_A   (NSTAGE * CHBYTES)     // 49152
#define SM_EE  (SM_A + MROWS * AROW)  // 65536
#define SMEM_TOTAL (SM_EE + KCODES * 4)   // 98304

__device__ __align__(256) __half g_A[(size_t)NPTS * DDIM];
__device__ __align__(256) __half g_B[(size_t)KCODES * DDIM];
__device__ float  g_zz[NPTS];
__device__ float  g_ee[KCODES];
__device__ float  g_eeC[KCODES];      // 65536 - 16384*ee
__device__ int    g_eemax_i;
__device__ int    g_cand[NPTS][32];
__device__ int    g_ccnt[NPTS];
__device__ int    g_idx[NPTS];
__device__ double g_loss;

__device__ __forceinline__ uint32_t smem_u32(const void* p) {
    uint32_t a;
    asm("{ .reg .u64 t; cvta.to.shared.u64 t, %1; cvt.u32.u64 %0, t; }" : "=r"(a) : "l"(p));
    return a;
}
__device__ __forceinline__ void cp16(uint32_t dst, const void* src) {
    asm volatile("cp.async.cg.shared.global [%0], [%1], 16;" :: "r"(dst), "l"(src) : "memory");
}
#define CP_COMMIT() asm volatile("cp.async.commit_group;" ::: "memory")
#define CP_WAIT(n)  asm volatile("cp.async.wait_group %0;" :: "n"(n) : "memory")

#define LDMX4(r, addr) asm volatile( \
    "ldmatrix.sync.aligned.m8n8.x4.shared.b16 {%0,%1,%2,%3}, [%4];" \
    : "=r"((r)[0]), "=r"((r)[1]), "=r"((r)[2]), "=r"((r)[3]) : "r"(addr))

#define MMA(c, a, b0, b1) asm volatile( \
    "mma.sync.aligned.m16n8k16.row.col.f32.f16.f16.f32 " \
    "{%0,%1,%2,%3}, {%4,%5,%6,%7}, {%8,%9}, {%0,%1,%2,%3};" \
    : "+f"((c)[0]), "+f"((c)[1]), "+f"((c)[2]), "+f"((c)[3]) \
    : "r"((a)[0]), "r"((a)[1]), "r"((a)[2]), "r"((a)[3]), "r"(b0), "r"(b1))

// ---------------- 1) fp16 quantize (scaled) + global resets -------------------
__global__ void vq_split(const float* __restrict__ z, const float* __restrict__ e) {
    int t = blockIdx.x * blockDim.x + threadIdx.x;
    if (t == 0) { g_loss = 0.0; g_eemax_i = 0; }
    if (t < NPTS * DDIM) {
        g_A[t] = __float2half_rn(z[t] * 64.f);
    } else if (t < (NPTS + KCODES) * DDIM) {
        int u = t - NPTS * DDIM;
        g_B[u] = __float2half_rn(e[u] * 512.f);
    }
}

// ---------------- 2) norms (+ offset ee, global max ||e||^2) ------------------
__global__ void vq_norms(const float* __restrict__ z, const float* __restrict__ e) {
    int t = blockIdx.x * blockDim.x + threadIdx.x;
    if (t < NPTS) {
        const float* p = z + (size_t)t * DDIM;
        float s = 0.f;
        for (int k = 0; k < DDIM; k++) s = __fadd_rn(s, __fmul_rn(p[k], p[k]));
        g_zz[t] = s;
    } else if (t < NPTS + KCODES) {
        const float* p = e + (size_t)(t - NPTS) * DDIM;
        float s = 0.f;
        for (int k = 0; k < DDIM; k++) s = __fadd_rn(s, __fmul_rn(p[k], p[k]));
        g_ee[t - NPTS] = s;
        g_eeC[t - NPTS] = 65536.f - s * 16384.f;
        atomicMax(&g_eemax_i, __float_as_int(s));
    }
}

// ---------------- 3) pass 1: approx GEMM + quad-keyed top-2 -------------------
__global__ void __launch_bounds__(256, 2) vq_main() {
    extern __shared__ __align__(1024) char sm[];
    const uint32_t sbase = smem_u32(sm);
    const int tid = threadIdx.x, lane = tid & 31, wid = tid >> 5;
    const int wm = wid >> 1, wn = wid & 1;          // 4(M) x 2(N) warps
    const int row0 = blockIdx.x * MROWS;

    #pragma unroll
    for (int q = 0; q < 4; q++) {
        int i = tid + 256 * q;
        int m = i >> 3, g = i & 7;
        cp16(sbase + SM_A + m * AROW + ((g ^ (m & 7)) << 4),
             (const char*)g_A + (size_t)(row0 + m) * AROW + g * 16);
    }
    #pragma unroll
    for (int q = 0; q < 8; q++) {
        int i = tid + 256 * q;
        cp16(sbase + SM_EE + i * 16, (const char*)g_eeC + i * 16);
    }
    CP_COMMIT();

    auto load_chunk = [&](int c) {
        const char* src = (const char*)g_B + (size_t)c * CHROWS * AROW;
        uint32_t d0 = sbase + (uint32_t)(c % NSTAGE) * CHBYTES;
        #pragma unroll
        for (int q = 0; q < 2; q++) {
            int i = tid + 256 * q;
            int n = i >> 3, g = i & 7;
            cp16(d0 + n * AROW + ((g ^ (n & 7)) << 4),
                 src + (size_t)n * AROW + g * 16);
        }
        CP_COMMIT();
    };
    load_chunk(0); load_chunk(1); load_chunk(2); load_chunk(3);

    CP_WAIT(4);
    __syncthreads();

    // A fragments -> registers, once
    uint32_t aF[4][2][4];
    {
        const uint32_t abase = sbase + SM_A + (wm * 32 + (lane & 15)) * AROW;
        #pragma unroll
        for (int kc = 0; kc < 4; kc++) {
            const int agr = kc * 2 + (lane >> 4);
            const uint32_t aoff = (uint32_t)((agr ^ (lane & 7)) << 4);
            #pragma unroll
            for (int mt = 0; mt < 2; mt++)
                LDMX4(aF[kc][mt], abase + mt * (16 * AROW) + aoff);
        }
    }

    int v1[4], v2[4];                 // packed quad keys: bits&~255 | code
    #pragma unroll
    for (int r = 0; r < 4; r++) { v1[r] = 0; v2[r] = 0; }

    const uint32_t nbase = (wn * 32 + ((lane >> 4) & 1) * 8 + (lane & 7)) * AROW;
    const int cbase = wn * 32 + 2 * (lane & 3);

    auto compute = [&](int c) {
        const uint32_t bbase = sbase + (uint32_t)(c % NSTAGE) * CHBYTES + nbase;
        float2 e2[4];
        #pragma unroll
        for (int c8 = 0; c8 < 4; c8++)
            e2[c8] = *(const float2*)(sm + SM_EE + (c * 64 + cbase + c8 * 8) * 4);
        float acc[2][4][4];
        #pragma unroll
        for (int mt = 0; mt < 2; mt++)
            #pragma unroll
            for (int c8 = 0; c8 < 4; c8++) {
                acc[mt][c8][0] = e2[c8].x; acc[mt][c8][1] = e2[c8].y;
                acc[mt][c8][2] = e2[c8].x; acc[mt][c8][3] = e2[c8].y;
            }
        #pragma unroll
        for (int kc = 0; kc < 4; kc++) {
            uint32_t b[2][4];
            const int bgr = kc * 2 + ((lane >> 3) & 1);
            const uint32_t boff = (uint32_t)((bgr ^ (lane & 7)) << 4);
            #pragma unroll
            for (int np = 0; np < 2; np++)
                LDMX4(b[np], bbase + np * (16 * AROW) + boff);
            #pragma unroll
            for (int mt = 0; mt < 2; mt++)
                #pragma unroll
                for (int np = 0; np < 2; np++) {
                    MMA(acc[mt][2 * np],     aF[kc][mt], b[np][0], b[np][1]);
                    MMA(acc[mt][2 * np + 1], aF[kc][mt], b[np][2], b[np][3]);
                }
        }
        // quad keys: max over 4 values (u>0 so int order == float order)
        const int code0 = c * 2;
        #pragma unroll
        for (int mt = 0; mt < 2; mt++)
            #pragma unroll
            for (int h = 0; h < 2; h++) {
                const int r = mt * 2 + h;
                int q0 = max(max((int)__float_as_uint(acc[mt][0][2 * h]),
                                 (int)__float_as_uint(acc[mt][0][2 * h + 1])),
                             max((int)__float_as_uint(acc[mt][1][2 * h]),
                                 (int)__float_as_uint(acc[mt][1][2 * h + 1])));
                int q1 = max(max((int)__float_as_uint(acc[mt][2][2 * h]),
                                 (int)__float_as_uint(acc[mt][2][2 * h + 1])),
                             max((int)__float_as_uint(acc[mt][3][2 * h]),
                                 (int)__float_as_uint(acc[mt][3][2 * h + 1])));
                int k0 = (int)(((uint32_t)q0 & 0xFFFFFF00u) | (uint32_t)code0);
                int k1 = (int)(((uint32_t)q1 & 0xFFFFFF00u) | (uint32_t)(code0 + 1));
                int v1r = v1[r], v2r = v2[r];
                v2r = max(v2r, min(k0, v1r)); v1r = max(v1r, k0);
                v2r = max(v2r, min(k1, v1r)); v1r = max(v1r, k1);
                v1[r] = v1r; v2[r] = v2r;
            }
    };

    for (int p = 0; p < 64; p++) {
        if (p < 63) { CP_WAIT(2); } else { CP_WAIT(0); }
        __syncthreads();
        if (p < 62) { load_chunk(2 * p + 4); load_chunk(2 * p + 5); }
        compute(2 * p);
        compute(2 * p + 1);
    }

    __syncthreads();
    int* rk = (int*)(sm + SM_A);                // [128][16] packed quad keys
    #pragma unroll
    for (int r = 0; r < 4; r++) {
        int row_l = wm * 32 + (r >> 1) * 16 + (r & 1) * 8 + (lane >> 2);
        int slot = wn * 8 + (lane & 3) * 2;
        rk[row_l * 16 + slot]     = v1[r];
        rk[row_l * 16 + slot + 1] = v2[r];
    }
    __syncthreads();
    if (tid < MROWS) {
        int kmax = rk[tid * 16];
        #pragma unroll
        for (int s = 1; s < 16; s++) kmax = max(kmax, rk[tid * 16 + s]);
        float vmax = __uint_as_float((uint32_t)kmax & 0xFFFFFF00u);
        float eemax = __int_as_float(g_eemax_i);
        float W = 24.0f * sqrtf(g_zz[row0 + tid] * eemax) + 18.0f;
        uint32_t thr = __float_as_uint(vmax - W);
        int cnt = 0;
        #pragma unroll
        for (int s = 0; s < 16; s++) {
            uint32_t k = (uint32_t)rk[tid * 16 + s];
            if (k >= thr && cnt <= 28) {
                int code = k & 255;
                int cc = code >> 1, qh = code & 1;
                int wn_s = s >> 3, q = (s >> 1) & 3;
                int base = cc * 64 + wn_s * 32 + q * 2 + qh * 16;
                g_cand[row0 + tid][cnt]     = base;
                g_cand[row0 + tid][cnt + 1] = base + 1;
                g_cand[row0 + tid][cnt + 2] = base + 8;
                g_cand[row0 + tid][cnt + 3] = base + 9;
                cnt += 4;
            }
        }
        g_ccnt[row0 + tid] = cnt;
    }
}

// ---------------- 4) pass 2: exact refine (always; cnt >= 4) ------------------
__global__ void vq_refine(const float* __restrict__ z, const float* __restrict__ e) {
    int row = blockIdx.x * 8 + (threadIdx.x >> 5);
    int lane = threadIdx.x & 31;
    if (row >= NPTS) return;
    int cnt = g_ccnt[row];
    float zv1 = z[(size_t)row * DDIM + lane];
    float zv2 = z[(size_t)row * DDIM + 32 + lane];
    float zzv = g_zz[row];
    float bd = FLT_MAX; int besti = 0x7fffffff;
    for (int t = 0; t < cnt; t++) {
        int idx = g_cand[row][t];
        float p = __fmaf_rn(zv2, e[(size_t)idx * DDIM + 32 + lane],
                            __fmul_rn(zv1, e[(size_t)idx * DDIM + lane]));
        #pragma unroll
        for (int off = 16; off; off >>= 1)
            p += __shfl_xor_sync(0xffffffffu, p, off);
        float d = __fmaf_rn(-2.f, p, __fadd_rn(zzv, g_ee[idx]));
        if (d < bd || (d == bd && idx < besti)) { bd = d; besti = idx; }
    }
    if (lane == 0) g_idx[row] = besti;
}

// ---------------- 5) gather + loss -------------------------------------------
__global__ void vq_out(const float* __restrict__ z, const float* __restrict__ emb,
                       float* __restrict__ out_zq, float* __restrict__ out_idxf) {
    int t = blockIdx.x * blockDim.x + threadIdx.x;
    int nth = gridDim.x * blockDim.x;
    double s = 0.0;
    for (int e4 = t; e4 < NPTS * DDIM / 4; e4 += nth) {
        int row = e4 >> 4;
        float4 zv = ((const float4*)z)[e4];
        float4 ev = *(const float4*)(emb + (size_t)g_idx[row] * DDIM + (e4 & 15) * 4);
        float rx = __fadd_rn(ev.x, -zv.x), ry = __fadd_rn(ev.y, -zv.y);
        float rz = __fadd_rn(ev.z, -zv.z), rw = __fadd_rn(ev.w, -zv.w);
        if (out_zq) {
            float4 o;
            o.x = __fadd_rn(zv.x, rx); o.y = __fadd_rn(zv.y, ry);
            o.z = __fadd_rn(zv.z, rz); o.w = __fadd_rn(zv.w, rw);
            ((float4*)out_zq)[e4] = o;
        }
        s += (double)__fmul_rn(rx, rx) + (double)__fmul_rn(ry, ry)
           + (double)__fmul_rn(rz, rz) + (double)__fmul_rn(rw, rw);
    }
    if (out_idxf && t < NPTS) out_idxf[t] = (float)g_idx[t];
    __shared__ double sd[256];
    sd[threadIdx.x] = s;
    __syncthreads();
    for (int o = 128; o > 0; o >>= 1) {
        if (threadIdx.x < o) sd[threadIdx.x] += sd[threadIdx.x + o];
        __syncthreads();
    }
    if (threadIdx.x == 0) atomicAdd(&g_loss, sd[0]);
}

__global__ void vq_loss(float* __restrict__ out_loss) {
    float m = (float)g_loss / (float)(NPTS * DDIM);
    out_loss[0] = __fadd_rn(__fmul_rn(0.25f, m), m);
}

// ---------------- launch -----------------------------------------------------
extern "C" void kernel_launch(void* const* d_in, const int* in_sizes, int n_in,
                              void* d_out, int out_size) {
    const float* z   = (const float*)d_in[0];
    const float* emb = (const float*)d_in[1];
    if (n_in >= 2 && in_sizes[0] == KCODES * DDIM && in_sizes[1] == NPTS * DDIM) {
        const float* t = z; z = emb; emb = t;
    }
    float* out = (float*)d_out;
    float* out_zq = nullptr; float* out_idxf = nullptr; float* out_loss = nullptr;
    const int NZ = NPTS * DDIM;
    if (out_size >= NZ + NPTS + 1) { out_zq = out; out_idxf = out + NZ; out_loss = out + NZ + NPTS; }
    else if (out_size == NZ)   { out_zq = out; }
    else if (out_size == NPTS) { out_idxf = out; }
    else if (out_size == 1)    { out_loss = out; }
    else                       { out_zq = out; }

    cudaFuncSetAttribute(vq_main, cudaFuncAttributeMaxDynamicSharedMemorySize, SMEM_TOTAL);

    vq_split<<<((NPTS + KCODES) * DDIM + 255) / 256, 256>>>(z, emb);
    vq_norms<<<(NPTS + KCODES + 255) / 256, 256>>>(z, emb);
    vq_main<<<NPTS / MROWS, 256, SMEM_TOTAL>>>();
    vq_refine<<<NPTS / 8, 256>>>(z, emb);
    vq_out<<<1024, 256>>>(z, emb, out_zq, out_idxf);
    if (out_loss) vq_loss<<<1, 1>>>(out_loss);
}

// round 14
// speedup vs baseline: 1.6804x; 1.1184x over previous
#include <cuda_runtime.h>
#include <cuda_fp16.h>
#include <cstdint>
#include <cfloat>

#define NPTS   32768
#define DDIM   64
#define KCODES 8192
#define MROWS  128
#define AROW   128                    // bytes per row (64 fp16)
#define NSTAGE 6
#define CHROWS 64
#define CHBYTES (CHROWS * AROW)       // 8192
#define NCHUNK (KCODES / CHROWS)      // 128
#define SM_A   (NSTAGE * CHBYTES)     // 49152
#define SM_EE  (SM_A + MROWS * AROW)  // 65536
#define SMEM_TOTAL (SM_EE + KCODES * 4)   // 98304

__device__ __align__(256) __half g_A[(size_t)NPTS * DDIM];
__device__ __align__(256) __half g_B[(size_t)KCODES * DDIM];
__device__ float  g_zz[NPTS];
__device__ float  g_ee[KCODES];
__device__ float  g_eeC[KCODES];      // 65536 - 16384*ee
__device__ int    g_eemax_i;
__device__ int    g_cand[NPTS][32];
__device__ int    g_ccnt[NPTS];
__device__ int    g_idx[NPTS];
__device__ double g_loss;

__device__ __forceinline__ uint32_t smem_u32(const void* p) {
    uint32_t a;
    asm("{ .reg .u64 t; cvta.to.shared.u64 t, %1; cvt.u32.u64 %0, t; }" : "=r"(a) : "l"(p));
    return a;
}
__device__ __forceinline__ void cp16(uint32_t dst, const void* src) {
    asm volatile("cp.async.cg.shared.global [%0], [%1], 16;" :: "r"(dst), "l"(src) : "memory");
}
#define CP_COMMIT() asm volatile("cp.async.commit_group;" ::: "memory")
#define CP_WAIT(n)  asm volatile("cp.async.wait_group %0;" :: "n"(n) : "memory")

#define LDMX4(r, addr) asm volatile( \
    "ldmatrix.sync.aligned.m8n8.x4.shared.b16 {%0,%1,%2,%3}, [%4];" \
    : "=r"((r)[0]), "=r"((r)[1]), "=r"((r)[2]), "=r"((r)[3]) : "r"(addr))

#define MMA(c, a, b0, b1) asm volatile( \
    "mma.sync.aligned.m16n8k16.row.col.f32.f16.f16.f32 " \
    "{%0,%1,%2,%3}, {%4,%5,%6,%7}, {%8,%9}, {%0,%1,%2,%3};" \
    : "+f"((c)[0]), "+f"((c)[1]), "+f"((c)[2]), "+f"((c)[3]) \
    : "r"((a)[0]), "r"((a)[1]), "r"((a)[2]), "r"((a)[3]), "r"(b0), "r"(b1))

// ---------------- 1) fused prep: fp16 quantize + sequential norms -------------
// Blocks 0..127 handle z rows, 128..159 handle e rows; 4 sub-iters of 64 rows.
// Coalesced float4 loads -> SMEM (padded); per-row norm summed SEQUENTIALLY by
// one thread (matches the rounding recipe that has measured rel_err 0).
__global__ void vq_prep(const float* __restrict__ z, const float* __restrict__ e) {
    __shared__ float tile[64 * 65];
    const int tid = threadIdx.x;
    const bool isz = blockIdx.x < (NPTS / 256);
    const int r0 = isz ? blockIdx.x * 256 : (blockIdx.x - NPTS / 256) * 256;
    if (blockIdx.x == 0 && tid == 0) { g_loss = 0.0; g_eemax_i = 0; }
    const float* src = isz ? z : e;
    const float scale = isz ? 64.f : 512.f;

    for (int it = 0; it < 4; it++) {
        const int rr = r0 + it * 64;             // first row of this sub-iter
        __syncthreads();
        #pragma unroll
        for (int q = 0; q < 4; q++) {
            int i = tid + 256 * q;               // float4 index 0..1023
            int row = i >> 4, c4 = i & 15;
            float4 v = ((const float4*)(src + (size_t)(rr + row) * DDIM))[c4];
            tile[row * 65 + c4 * 4 + 0] = v.x;
            tile[row * 65 + c4 * 4 + 1] = v.y;
            tile[row * 65 + c4 * 4 + 2] = v.z;
            tile[row * 65 + c4 * 4 + 3] = v.w;
            __half2 h0 = __floats2half2_rn(v.x * scale, v.y * scale);
            __half2 h1 = __floats2half2_rn(v.z * scale, v.w * scale);
            __half* dst = (isz ? g_A : g_B) + (size_t)(rr + row) * DDIM + c4 * 4;
            *(__half2*)dst = h0;
            *(__half2*)(dst + 2) = h1;
        }
        __syncthreads();
        if (tid < 64) {
            const float* p = tile + tid * 65;
            float s = 0.f;
            for (int k = 0; k < DDIM; k++) s = __fadd_rn(s, __fmul_rn(p[k], p[k]));
            int row = rr + tid;
            if (isz) {
                g_zz[row] = s;
            } else {
                g_ee[row] = s;
                g_eeC[row] = 65536.f - s * 16384.f;
                atomicMax(&g_eemax_i, __float_as_int(s));
            }
        }
    }
}

// ---------------- 2) pass 1: approx GEMM + quad-keyed top-2 -------------------
__global__ void __launch_bounds__(256, 2) vq_main() {
    extern __shared__ __align__(1024) char sm[];
    const uint32_t sbase = smem_u32(sm);
    const int tid = threadIdx.x, lane = tid & 31, wid = tid >> 5;
    const int wm = wid >> 1, wn = wid & 1;          // 4(M) x 2(N) warps
    const int row0 = blockIdx.x * MROWS;

    #pragma unroll
    for (int q = 0; q < 4; q++) {
        int i = tid + 256 * q;
        int m = i >> 3, g = i & 7;
        cp16(sbase + SM_A + m * AROW + ((g ^ (m & 7)) << 4),
             (const char*)g_A + (size_t)(row0 + m) * AROW + g * 16);
    }
    #pragma unroll
    for (int q = 0; q < 8; q++) {
        int i = tid + 256 * q;
        cp16(sbase + SM_EE + i * 16, (const char*)g_eeC + i * 16);
    }
    CP_COMMIT();

    auto load_chunk = [&](int c) {
        const char* src = (const char*)g_B + (size_t)c * CHROWS * AROW;
        uint32_t d0 = sbase + (uint32_t)(c % NSTAGE) * CHBYTES;
        #pragma unroll
        for (int q = 0; q < 2; q++) {
            int i = tid + 256 * q;
            int n = i >> 3, g = i & 7;
            cp16(d0 + n * AROW + ((g ^ (n & 7)) << 4),
                 src + (size_t)n * AROW + g * 16);
        }
        CP_COMMIT();
    };
    load_chunk(0); load_chunk(1); load_chunk(2); load_chunk(3);

    CP_WAIT(4);
    __syncthreads();

    // A fragments -> registers, once
    uint32_t aF[4][2][4];
    {
        const uint32_t abase = sbase + SM_A + (wm * 32 + (lane & 15)) * AROW;
        #pragma unroll
        for (int kc = 0; kc < 4; kc++) {
            const int agr = kc * 2 + (lane >> 4);
            const uint32_t aoff = (uint32_t)((agr ^ (lane & 7)) << 4);
            #pragma unroll
            for (int mt = 0; mt < 2; mt++)
                LDMX4(aF[kc][mt], abase + mt * (16 * AROW) + aoff);
        }
    }

    int v1[4], v2[4];                 // packed quad keys: bits&~255 | code
    #pragma unroll
    for (int r = 0; r < 4; r++) { v1[r] = 0; v2[r] = 0; }

    const uint32_t nbase = (wn * 32 + ((lane >> 4) & 1) * 8 + (lane & 7)) * AROW;
    const int cbase = wn * 32 + 2 * (lane & 3);

    auto compute = [&](int c) {
        const uint32_t bbase = sbase + (uint32_t)(c % NSTAGE) * CHBYTES + nbase;
        float2 e2[4];
        #pragma unroll
        for (int c8 = 0; c8 < 4; c8++)
            e2[c8] = *(const float2*)(sm + SM_EE + (c * 64 + cbase + c8 * 8) * 4);
        float acc[2][4][4];
        #pragma unroll
        for (int mt = 0; mt < 2; mt++)
            #pragma unroll
            for (int c8 = 0; c8 < 4; c8++) {
                acc[mt][c8][0] = e2[c8].x; acc[mt][c8][1] = e2[c8].y;
                acc[mt][c8][2] = e2[c8].x; acc[mt][c8][3] = e2[c8].y;
            }
        #pragma unroll
        for (int kc = 0; kc < 4; kc++) {
            uint32_t b[2][4];
            const int bgr = kc * 2 + ((lane >> 3) & 1);
            const uint32_t boff = (uint32_t)((bgr ^ (lane & 7)) << 4);
            #pragma unroll
            for (int np = 0; np < 2; np++)
                LDMX4(b[np], bbase + np * (16 * AROW) + boff);
            #pragma unroll
            for (int mt = 0; mt < 2; mt++)
                #pragma unroll
                for (int np = 0; np < 2; np++) {
                    MMA(acc[mt][2 * np],     aF[kc][mt], b[np][0], b[np][1]);
                    MMA(acc[mt][2 * np + 1], aF[kc][mt], b[np][2], b[np][3]);
                }
        }
        // quad keys: max over 4 values (u>0 so int order == float order)
        const int code0 = c * 2;
        #pragma unroll
        for (int mt = 0; mt < 2; mt++)
            #pragma unroll
            for (int h = 0; h < 2; h++) {
                const int r = mt * 2 + h;
                int q0 = max(max((int)__float_as_uint(acc[mt][0][2 * h]),
                                 (int)__float_as_uint(acc[mt][0][2 * h + 1])),
                             max((int)__float_as_uint(acc[mt][1][2 * h]),
                                 (int)__float_as_uint(acc[mt][1][2 * h + 1])));
                int q1 = max(max((int)__float_as_uint(acc[mt][2][2 * h]),
                                 (int)__float_as_uint(acc[mt][2][2 * h + 1])),
                             max((int)__float_as_uint(acc[mt][3][2 * h]),
                                 (int)__float_as_uint(acc[mt][3][2 * h + 1])));
                int k0 = (int)(((uint32_t)q0 & 0xFFFFFF00u) | (uint32_t)code0);
                int k1 = (int)(((uint32_t)q1 & 0xFFFFFF00u) | (uint32_t)(code0 + 1));
                int v1r = v1[r], v2r = v2[r];
                v2r = max(v2r, min(k0, v1r)); v1r = max(v1r, k0);
                v2r = max(v2r, min(k1, v1r)); v1r = max(v1r, k1);
                v1[r] = v1r; v2[r] = v2r;
            }
    };

    for (int p = 0; p < 64; p++) {
        if (p < 63) { CP_WAIT(2); } else { CP_WAIT(0); }
        __syncthreads();
        if (p < 62) { load_chunk(2 * p + 4); load_chunk(2 * p + 5); }
        compute(2 * p);
        compute(2 * p + 1);
    }

    __syncthreads();
    int* rk = (int*)(sm + SM_A);                // [128][16] packed quad keys
    #pragma unroll
    for (int r = 0; r < 4; r++) {
        int row_l = wm * 32 + (r >> 1) * 16 + (r & 1) * 8 + (lane >> 2);
        int slot = wn * 8 + (lane & 3) * 2;
        rk[row_l * 16 + slot]     = v1[r];
        rk[row_l * 16 + slot + 1] = v2[r];
    }
    __syncthreads();
    if (tid < MROWS) {
        int kmax = rk[tid * 16];
        #pragma unroll
        for (int s = 1; s < 16; s++) kmax = max(kmax, rk[tid * 16 + s]);
        float vmax = __uint_as_float((uint32_t)kmax & 0xFFFFFF00u);
        float eemax = __int_as_float(g_eemax_i);
        float W = 24.0f * sqrtf(g_zz[row0 + tid] * eemax) + 18.0f;
        uint32_t thr = __float_as_uint(vmax - W);
        int cnt = 0;
        #pragma unroll
        for (int s = 0; s < 16; s++) {
            uint32_t k = (uint32_t)rk[tid * 16 + s];
            if (k >= thr && cnt <= 28) {
                int code = k & 255;
                int cc = code >> 1, qh = code & 1;
                int wn_s = s >> 3, q = (s >> 1) & 3;
                int base = cc * 64 + wn_s * 32 + q * 2 + qh * 16;
                g_cand[row0 + tid][cnt]     = base;
                g_cand[row0 + tid][cnt + 1] = base + 1;
                g_cand[row0 + tid][cnt + 2] = base + 8;
                g_cand[row0 + tid][cnt + 3] = base + 9;
                cnt += 4;
            }
        }
        g_ccnt[row0 + tid] = cnt;
    }
}

// ---------------- 3) pass 2: exact refine, 4 candidates in parallel -----------
// cnt is always a positive multiple of 4. 8 lanes per candidate; octet shfl
// reduce; cross-octet min with lowest-index tie-break.
__global__ void vq_refine(const float* __restrict__ z, const float* __restrict__ e) {
    int row = blockIdx.x * 8 + (threadIdx.x >> 5);
    int lane = threadIdx.x & 31;
    if (row >= NPTS) return;
    const int j = lane >> 3, sub = lane & 7;
    float zf[8];
    #pragma unroll
    for (int i = 0; i < 8; i++) zf[i] = z[(size_t)row * DDIM + sub * 8 + i];
    const float zzv = g_zz[row];
    const int cnt = g_ccnt[row];
    float bd = FLT_MAX; int besti = 0x7fffffff;
    for (int t0 = 0; t0 < cnt; t0 += 4) {
        int idx = g_cand[row][t0 + j];
        const float* ep = e + (size_t)idx * DDIM + sub * 8;
        float p = 0.f;
        #pragma unroll
        for (int i = 0; i < 8; i++) p = __fmaf_rn(zf[i], ep[i], p);
        p += __shfl_xor_sync(0xffffffffu, p, 1);
        p += __shfl_xor_sync(0xffffffffu, p, 2);
        p += __shfl_xor_sync(0xffffffffu, p, 4);
        float d = __fmaf_rn(-2.f, p, __fadd_rn(zzv, g_ee[idx]));
        #pragma unroll
        for (int off = 8; off <= 16; off <<= 1) {
            float od = __shfl_xor_sync(0xffffffffu, d, off);
            int   oi = __shfl_xor_sync(0xffffffffu, idx, off);
            if (od < d || (od == d && oi < idx)) { d = od; idx = oi; }
        }
        if (d < bd || (d == bd && idx < besti)) { bd = d; besti = idx; }
    }
    if (lane == 0) g_idx[row] = besti;
}

// ---------------- 4) gather + loss -------------------------------------------
__global__ void vq_out(const float* __restrict__ z, const float* __restrict__ emb,
                       float* __restrict__ out_zq, float* __restrict__ out_idxf) {
    int t = blockIdx.x * blockDim.x + threadIdx.x;
    int nth = gridDim.x * blockDim.x;
    double s = 0.0;
    for (int e4 = t; e4 < NPTS * DDIM / 4; e4 += nth) {
        int row = e4 >> 4;
        float4 zv = ((const float4*)z)[e4];
        float4 ev = *(const float4*)(emb + (size_t)g_idx[row] * DDIM + (e4 & 15) * 4);
        float rx = __fadd_rn(ev.x, -zv.x), ry = __fadd_rn(ev.y, -zv.y);
        float rz = __fadd_rn(ev.z, -zv.z), rw = __fadd_rn(ev.w, -zv.w);
        if (out_zq) {
            float4 o;
            o.x = __fadd_rn(zv.x, rx); o.y = __fadd_rn(zv.y, ry);
            o.z = __fadd_rn(zv.z, rz); o.w = __fadd_rn(zv.w, rw);
            ((float4*)out_zq)[e4] = o;
        }
        s += (double)__fmul_rn(rx, rx) + (double)__fmul_rn(ry, ry)
           + (double)__fmul_rn(rz, rz) + (double)__fmul_rn(rw, rw);
    }
    if (out_idxf && t < NPTS) out_idxf[t] = (float)g_idx[t];
    __shared__ double sd[256];
    sd[threadIdx.x] = s;
    __syncthreads();
    for (int o = 128; o > 0; o >>= 1) {
        if (threadIdx.x < o) sd[threadIdx.x] += sd[threadIdx.x + o];
        __syncthreads();
    }
    if (threadIdx.x == 0) atomicAdd(&g_loss, sd[0]);
}

__global__ void vq_loss(float* __restrict__ out_loss) {
    float m = (float)g_loss / (float)(NPTS * DDIM);
    out_loss[0] = __fadd_rn(__fmul_rn(0.25f, m), m);
}

// ---------------- launch -----------------------------------------------------
extern "C" void kernel_launch(void* const* d_in, const int* in_sizes, int n_in,
                              void* d_out, int out_size) {
    const float* z   = (const float*)d_in[0];
    const float* emb = (const float*)d_in[1];
    if (n_in >= 2 && in_sizes[0] == KCODES * DDIM && in_sizes[1] == NPTS * DDIM) {
        const float* t = z; z = emb; emb = t;
    }
    float* out = (float*)d_out;
    float* out_zq = nullptr; float* out_idxf = nullptr; float* out_loss = nullptr;
    const int NZ = NPTS * DDIM;
    if (out_size >= NZ + NPTS + 1) { out_zq = out; out_idxf = out + NZ; out_loss = out + NZ + NPTS; }
    else if (out_size == NZ)   { out_zq = out; }
    else if (out_size == NPTS) { out_idxf = out; }
    else if (out_size == 1)    { out_loss = out; }
    else                       { out_zq = out; }

    cudaFuncSetAttribute(vq_main, cudaFuncAttributeMaxDynamicSharedMemorySize, SMEM_TOTAL);

    vq_prep<<<(NPTS + KCODES) / 256, 256>>>(z, emb);
    vq_main<<<NPTS / MROWS, 256, SMEM_TOTAL>>>();
    vq_refine<<<NPTS / 8, 256>>>(z, emb);
    vq_out<<<1024, 256>>>(z, emb, out_zq, out_idxf);
    if (out_loss) vq_loss<<<1, 1>>>(out_loss);
}